// round 11
// baseline (speedup 1.0000x reference)
#include <cuda_runtime.h>

// WOS 3x3 filter — key-only sorting network, TWO independent sorts per thread.
//
// R7-R9 analysis: executed instrs/thread ~2000 regardless of trims; issue
// pinned at 0.6/SMSP with alu at 75% of ceiling, insensitive to occupancy.
// Diagnosis: per-warp stall exposure that more warps don't fill. Fix: double
// the ILP inside each warp — each thread sorts 2 pixels (108 key regs, fully
// unrolled, const-indexed). Straight-line fast path lets ptxas interleave the
// two epilogue dependency chains.

#define NCH 16
#define DD 54
#define HH 64
#define WW 64
#define PIX_PER_BLK 16
#define NTHREADS 128
#define TILE_COLS (PIX_PER_BLK + 2)    // 18
#define TILE_ELEMS (3 * 3 * TILE_COLS) // 162
#define WSTRIDE 65
#define ZTOL 1e-6f

__device__ __forceinline__ unsigned sortable_bits(float f) {
    unsigned u = __float_as_uint(f);
    return u ^ (((unsigned)(((int)u) >> 31)) | 0x80000000u);
}

// ---- epilogues: inlined, fully unrolled, key array stays in registers ----
__device__ __forceinline__ float fast_epi(const unsigned (&key)[DD],
                                          const float* __restrict__ wrow,
                                          const float* __restrict__ mrow,
                                          const int*   __restrict__ toff_s,
                                          const float* __restrict__ tile_s,
                                          int basecol, float bs)
{
    float acc = 0.0f;
    unsigned selk = key[0];
    #pragma unroll
    for (int k2 = 0; k2 < DD; k2++) {
        const unsigned ck = key[k2];
        acc += wrow[ck & 63u];
        if (acc <= bs) selk = ck;
    }
    const int d = 63 - (int)(selk & 63u);
    const float t = tile_s[toff_s[d] + basecol];
    const float m = mrow[d];
    return (d < 27) ? (t + m) : (m - t);
}

__device__ __forceinline__ float repair_epi(const unsigned (&key)[DD],
                                            const float* __restrict__ wrow,
                                            const float* __restrict__ mrow,
                                            const int*   __restrict__ toff_s,
                                            const float* __restrict__ tile_s,
                                            int basecol, float bs)
{
    float acc = 0.0f, ans = 0.0f;
    bool seen = false;

    unsigned pk = key[0];
    int dp = 63 - (int)(pk & 63u);
    float tp = tile_s[toff_s[dp] + basecol];
    float mp = mrow[dp];
    float pv = (dp < 27) ? (tp + mp) : (mp - tp);
    float pw = wrow[pk & 63u];

    #pragma unroll
    for (int k2 = 1; k2 < DD; k2++) {
        const unsigned ck = key[k2];
        const unsigned sl = ck & 63u;
        const int dc = 63 - (int)sl;
        const float tc = tile_s[toff_s[dc] + basecol];
        const float mc = mrow[dc];
        const float cv = (dc < 27) ? (tc + mc) : (mc - tc);
        const float cw = wrow[sl];

        const bool sw = ((pk ^ ck) < 64u) && (cv > pv);
        const float ev = sw ? cv : pv;
        const float ew = sw ? cw : pw;
        pv = sw ? pv : cv;
        pw = sw ? pw : cw;
        pk = ck;

        const bool nz = ew > ZTOL;
        if (nz) acc += ew;
        if (nz && ((acc <= bs) || !seen)) ans = ev;
        seen |= nz;
    }
    {
        const bool nz = pw > ZTOL;
        if (nz) acc += pw;
        if (nz && ((acc <= bs) || !seen)) ans = pv;
    }
    return ans;
}

__global__ __launch_bounds__(NTHREADS, 3)
void wos_kernel(const float* __restrict__ x,
                const float* __restrict__ mask,
                const float* __restrict__ weight,
                const float* __restrict__ bias,
                float* __restrict__ out)
{
    __shared__ float tile_s[TILE_ELEMS];
    __shared__ float msk_s[NCH * DD];
    __shared__ float w2_s[NCH * WSTRIDE];
    __shared__ float bias_s[NCH];
    __shared__ int   toff_s[DD];
    __shared__ int   tiny_s;

    const int tid = threadIdx.x;
    const int c  = tid & (NCH - 1);
    const int ty = tid >> 4;                // 0..7  (pixel A col; B = ty+8)

    const int pix0 = blockIdx.x * PIX_PER_BLK;
    const int b    = pix0 >> 12;
    const int rem  = pix0 & 4095;
    const int h    = rem >> 6;
    const int w0   = rem & 63;              // multiple of 16

    if (tid == 0) tiny_s = 0;

    // ---- cooperative staging ----
    #pragma unroll
    for (int idx = tid; idx < NCH * DD; idx += NTHREADS) {
        const int cw = idx / DD;
        const int d  = idx - cw * DD;
        const float wgt = weight[idx];
        msk_s[idx] = mask[idx];
        w2_s[cw * WSTRIDE + (53 - d)] = wgt;
        if (wgt <= ZTOL) tiny_s = 1;
    }
    if (tid < NCH) bias_s[tid] = bias[tid];
    if (tid < DD) {
        const int d0 = (tid < 27) ? tid : tid - 27;
        toff_s[tid] = ((d0 / 9) * 3 + ((d0 / 3) % 3)) * TILE_COLS + (d0 % 3);
    }
    #pragma unroll
    for (int idx = tid; idx < TILE_ELEMS; idx += NTHREADS) {
        int cc  = idx / (3 * TILE_COLS);
        int r   = (idx / TILE_COLS) % 3;
        int col = idx % TILE_COLS;
        int gh = h + r - 1;
        int gw = w0 + col - 1;
        float v = 0.0f;
        if (gh >= 0 && gh < HH && gw >= 0 && gw < WW)
            v = x[((b * 3 + cc) * HH + gh) * WW + gw];
        tile_s[idx] = v;
    }
    __syncthreads();

    const float* wrow = &w2_s[c * WSTRIDE] - 10;
    const float* mrow = &msk_s[c * DD];
    const bool   tinyw = (tiny_s != 0);
    const float  bs = bias_s[c];
    const int    baseA = ty;
    const int    baseB = ty + 8;

    // ---- build both key sets ----
    unsigned kA[DD], kB[DD];
    #pragma unroll
    for (int d0 = 0; d0 < 27; d0++) {
        const int cc = d0 / 9;
        const int r  = (d0 / 3) % 3;
        const int j  = d0 % 3;
        const int tbase = (cc * 3 + r) * TILE_COLS + j;
        const float m1 = mrow[d0];
        const float m2 = mrow[27 + d0];

        float tA  = tile_s[tbase + baseA];
        float fpA = tA + m1, fmA = m2 - tA;
        kA[d0]      = (sortable_bits(fpA) & 0xFFFFFFC0u) | (unsigned)(63 - d0);
        kA[27 + d0] = (sortable_bits(fmA) & 0xFFFFFFC0u) | (unsigned)(36 - d0);

        float tB  = tile_s[tbase + baseB];
        float fpB = tB + m1, fmB = m2 - tB;
        kB[d0]      = (sortable_bits(fpB) & 0xFFFFFFC0u) | (unsigned)(63 - d0);
        kB[27 + d0] = (sortable_bits(fmB) & 0xFFFFFFC0u) | (unsigned)(36 - d0);
    }

    // ---- interleaved Batcher odd-even merge sorts (descending, n=54) ----
#define CE(KK, A, B)                                 \
    do {                                             \
        unsigned ka = KK[A], kb = KK[B];             \
        KK[A] = umax(ka, kb);                        \
        KK[B] = umin(ka, kb);                        \
    } while (0)

#define PASS1(KK, P, K)                                                     \
    _Pragma("unroll")                                                       \
    for (int j = (K) % (P); j + (K) < DD; j += 2 * (K)) {                   \
        _Pragma("unroll")                                                   \
        for (int i = 0; i < (K); i++) {                                     \
            const int a  = i + j;                                           \
            const int bb = i + j + (K);                                     \
            if (bb < DD && (a / (2 * (P))) == (bb / (2 * (P))))             \
                CE(KK, a, bb);                                              \
        }                                                                   \
    }

#define PASS2(P, K) PASS1(kA, P, K) PASS1(kB, P, K)

    PASS2(1, 1)
    PASS2(2, 2)  PASS2(2, 1)
    PASS2(4, 4)  PASS2(4, 2)  PASS2(4, 1)
    PASS2(8, 8)  PASS2(8, 4)  PASS2(8, 2)  PASS2(8, 1)
    PASS2(16, 16) PASS2(16, 8) PASS2(16, 4) PASS2(16, 2) PASS2(16, 1)
    PASS2(32, 32) PASS2(32, 16) PASS2(32, 8) PASS2(32, 4) PASS2(32, 2) PASS2(32, 1)

#undef PASS2
#undef PASS1
#undef CE

    // ---- tie detection for both sorts ----
    unsigned ta = 0xFFFFFFFFu, tb = 0xFFFFFFFFu;
    #pragma unroll
    for (int k2 = 0; k2 < DD - 1; k2++) {
        ta = umin(ta, kA[k2] ^ kA[k2 + 1]);
        tb = umin(tb, kB[k2] ^ kB[k2 + 1]);
    }
    const bool slowA = __any_sync(0xFFFFFFFFu, ta < 64u) | tinyw;
    const bool slowB = __any_sync(0xFFFFFFFFu, tb < 64u) | tinyw;

    float yA, yB;
    if (!slowA && !slowB) {
        // common case: both fast epilogues in one straight-line region
        yA = fast_epi(kA, wrow, mrow, toff_s, tile_s, baseA, bs);
        yB = fast_epi(kB, wrow, mrow, toff_s, tile_s, baseB, bs);
    } else {
        yA = slowA ? repair_epi(kA, wrow, mrow, toff_s, tile_s, baseA, bs)
                   : fast_epi(kA, wrow, mrow, toff_s, tile_s, baseA, bs);
        yB = slowB ? repair_epi(kB, wrow, mrow, toff_s, tile_s, baseB, bs)
                   : fast_epi(kB, wrow, mrow, toff_s, tile_s, baseB, bs);
    }

    // raw .view(B, NC, H, W): channel fastest -> coalesced
    const int obase = b * (NCH * HH * WW) + (h * WW + w0) * NCH + c;
    out[obase + baseA * NCH] = yA;
    out[obase + baseB * NCH] = yB;
}

extern "C" void kernel_launch(void* const* d_in, const int* in_sizes, int n_in,
                              void* d_out, int out_size)
{
    const float* x      = (const float*)d_in[0];
    const float* mask   = (const float*)d_in[1];
    const float* weight = (const float*)d_in[2];
    const float* bias   = (const float*)d_in[3];
    float* out = (float*)d_out;

    const int B = in_sizes[0] / (3 * HH * WW);
    const int npix = B * HH * WW;
    dim3 grid(npix / PIX_PER_BLK);
    wos_kernel<<<grid, NTHREADS>>>(x, mask, weight, bias, out);
}

// round 12
// speedup vs baseline: 1.6364x; 1.6364x over previous
#include <cuda_runtime.h>

// WOS 3x3 filter — FLOAT-key sorting network (no sortable-uint transform).
//
// key_bits = (bits(mx) & ~63) | slot, slot = 63-d, sorted AS FLOAT with
// fmaxf/fminf (FMNMX). IEEE ordering == value ordering for distinct top-26
// bits; truncation ties (incl. the flipped intra-tie order for negatives)
// are detected by bit-XOR < 64 on adjacent sorted keys and corrected by the
// full-precision repair path (proven rel_err 0.0 since R6).
// Saves the 2-op sign transform per element (-108 alu/thread) vs R9.

#define NCH 16
#define DD 54
#define HH 64
#define WW 64
#define PIX_PER_BLK 8
#define NTHREADS 128
#define TILE_COLS (PIX_PER_BLK + 2)    // 10
#define TILE_ELEMS (3 * 3 * TILE_COLS) // 90
#define WSTRIDE 65
#define ZTOL 1e-6f

__global__ __launch_bounds__(NTHREADS, 7)
void wos_kernel(const float* __restrict__ x,
                const float* __restrict__ mask,
                const float* __restrict__ weight,
                const float* __restrict__ bias,
                float* __restrict__ out)
{
    __shared__ float  tile_s[TILE_ELEMS];
    __shared__ float2 mp_s[NCH * 27];       // (mask[d0], mask[27+d0]) pairs
    __shared__ float  w2_s[NCH * WSTRIDE];  // slot-indexed weights
    __shared__ float  bias_s[NCH];
    __shared__ int    toff_s[DD];
    __shared__ int    tiny_s;

    const int tid = threadIdx.x;
    const int c  = tid & (NCH - 1);
    const int ty = tid >> 4;

    const int pix0 = blockIdx.x * PIX_PER_BLK;
    const int b    = pix0 >> 12;
    const int rem  = pix0 & 4095;
    const int h    = rem >> 6;
    const int w0   = rem & 63;

    if (tid == 0) tiny_s = 0;

    // ---- cooperative staging ----
    float* mflat_all = (float*)mp_s;
    #pragma unroll
    for (int idx = tid; idx < NCH * DD; idx += NTHREADS) {
        const int cw = idx / DD;
        const int d  = idx - cw * DD;
        const float wgt = weight[idx];
        // mask pair layout: [cw*54 + 2*d0]   = mask[cw][d0]       (d0 < 27)
        //                   [cw*54 + 2*d0+1] = mask[cw][27+d0]
        const int dst = cw * DD + ((d < 27) ? (2 * d) : (2 * d - 53));
        mflat_all[dst] = mask[idx];
        w2_s[cw * WSTRIDE + (53 - d)] = wgt;   // slot 63-d stored at slot-10
        if (wgt <= ZTOL) tiny_s = 1;
    }
    if (tid < NCH) bias_s[tid] = bias[tid];
    if (tid < DD) {
        const int d0 = (tid < 27) ? tid : tid - 27;
        toff_s[tid] = ((d0 / 9) * 3 + ((d0 / 3) % 3)) * TILE_COLS + (d0 % 3);
    }
    #pragma unroll
    for (int idx = tid; idx < TILE_ELEMS; idx += NTHREADS) {
        int cc  = idx / (3 * TILE_COLS);
        int r   = (idx / TILE_COLS) % 3;
        int col = idx % TILE_COLS;
        int gh = h + r - 1;
        int gw = w0 + col - 1;
        float v = 0.0f;
        if (gh >= 0 && gh < HH && gw >= 0 && gw < WW)
            v = x[((b * 3 + cc) * HH + gh) * WW + gw];
        tile_s[idx] = v;
    }
    __syncthreads();

    const float*  wrow  = &w2_s[c * WSTRIDE] - 10;   // index by slot [10,63]
    const float2* mprow = &mp_s[c * 27];
    const float*  mflat = (const float*)mprow;
    const bool    tinyw = (tiny_s != 0);
    const float   bs = bias_s[c];

    // ---- build float keys (regs only) ----
    float key[DD];
    #pragma unroll
    for (int d0 = 0; d0 < 27; d0++) {
        const int cc = d0 / 9;
        const int r  = (d0 / 3) % 3;
        const int j  = d0 % 3;
        const float2 mm = mprow[d0];                       // LDS.64
        float t  = tile_s[(cc * 3 + r) * TILE_COLS + ty + j];
        float fp = t + mm.x;                // element d0    -> slot 63-d0
        float fm = mm.y - t;                // element 27+d0 -> slot 36-d0
        unsigned up = __float_as_uint(fp);
        unsigned um = __float_as_uint(fm);
        key[d0]      = __uint_as_float((up | 63u) ^ (unsigned)(63 ^ (63 - d0)));
        key[27 + d0] = __uint_as_float((um | 63u) ^ (unsigned)(63 ^ (36 - d0)));
    }

    // ---- Batcher odd-even merge sort, descending, n=54, FMNMX CEs ----
#define CE(A, B)                                 \
    do {                                         \
        float ka = key[A], kb = key[B];          \
        key[A] = fmaxf(ka, kb);                  \
        key[B] = fminf(ka, kb);                  \
    } while (0)

#define PASS(P, K)                                                          \
    _Pragma("unroll")                                                       \
    for (int j = (K) % (P); j + (K) < DD; j += 2 * (K)) {                   \
        _Pragma("unroll")                                                   \
        for (int i = 0; i < (K); i++) {                                     \
            const int a  = i + j;                                           \
            const int bb = i + j + (K);                                     \
            if (bb < DD && (a / (2 * (P))) == (bb / (2 * (P))))             \
                CE(a, bb);                                                  \
        }                                                                   \
    }

    PASS(1, 1)
    PASS(2, 2)  PASS(2, 1)
    PASS(4, 4)  PASS(4, 2)  PASS(4, 1)
    PASS(8, 8)  PASS(8, 4)  PASS(8, 2)  PASS(8, 1)
    PASS(16, 16) PASS(16, 8) PASS(16, 4) PASS(16, 2) PASS(16, 1)
    PASS(32, 32) PASS(32, 16) PASS(32, 8) PASS(32, 4) PASS(32, 2) PASS(32, 1)

#undef PASS
#undef CE

    // ---- tie detection: adjacent keys sharing top-26 bits (bit XOR) ----
    unsigned t0 = 0xFFFFFFFFu, t1 = 0xFFFFFFFFu, t2 = 0xFFFFFFFFu, t3 = 0xFFFFFFFFu;
    #pragma unroll
    for (int k2 = 0; k2 + 4 <= DD - 1; k2 += 4) {
        t0 = umin(t0, __float_as_uint(key[k2])     ^ __float_as_uint(key[k2 + 1]));
        t1 = umin(t1, __float_as_uint(key[k2 + 1]) ^ __float_as_uint(key[k2 + 2]));
        t2 = umin(t2, __float_as_uint(key[k2 + 2]) ^ __float_as_uint(key[k2 + 3]));
        t3 = umin(t3, __float_as_uint(key[k2 + 3]) ^ __float_as_uint(key[k2 + 4]));
    }
    t0 = umin(t0, __float_as_uint(key[52]) ^ __float_as_uint(key[53]));
    const unsigned tmin = umin(umin(t0, t1), umin(t2, t3));
    const bool slow = __any_sync(0xFFFFFFFFu, tmin < 64u) | tinyw;

    float y;
    if (!slow) {
        // ---- fast path (exact): weights only; recompute 1 value at end ----
        float acc = 0.0f;
        unsigned selk = __float_as_uint(key[0]);
        #pragma unroll
        for (int k2 = 0; k2 < DD; k2++) {
            const unsigned ck = __float_as_uint(key[k2]);
            acc += wrow[ck & 63u];
            if (acc <= bs) selk = ck;
        }
        const int d = 63 - (int)(selk & 63u);
        const float t = tile_s[toff_s[d] + ty];
        const float m = mflat[(d < 27) ? (2 * d) : (2 * d - 53)];
        y = (d < 27) ? (t + m) : (m - t);
    } else {
        // ---- repair path: full-precision adjacent-tie repair + nz checks ----
        float acc = 0.0f, ans = 0.0f;
        bool seen = false;

        unsigned pk = __float_as_uint(key[0]);
        int dp = 63 - (int)(pk & 63u);
        float tp = tile_s[toff_s[dp] + ty];
        float mp = mflat[(dp < 27) ? (2 * dp) : (2 * dp - 53)];
        float pv = (dp < 27) ? (tp + mp) : (mp - tp);
        float pw = wrow[pk & 63u];

        #pragma unroll
        for (int k2 = 1; k2 < DD; k2++) {
            const unsigned ck = __float_as_uint(key[k2]);
            const unsigned sl = ck & 63u;
            const int dc = 63 - (int)sl;
            const float tc = tile_s[toff_s[dc] + ty];
            const float mc = mflat[(dc < 27) ? (2 * dc) : (2 * dc - 53)];
            const float cv = (dc < 27) ? (tc + mc) : (mc - tc);
            const float cw = wrow[sl];

            const bool sw = ((pk ^ ck) < 64u) && (cv > pv);
            const float ev = sw ? cv : pv;
            const float ew = sw ? cw : pw;
            pv = sw ? pv : cv;
            pw = sw ? pw : cw;
            pk = ck;

            const bool nz = ew > ZTOL;
            if (nz) acc += ew;
            if (nz && ((acc <= bs) || !seen)) ans = ev;
            seen |= nz;
        }
        {
            const bool nz = pw > ZTOL;
            if (nz) acc += pw;
            if (nz && ((acc <= bs) || !seen)) ans = pv;
        }
        y = ans;
    }

    // raw .view(B, NC, H, W): channel fastest -> coalesced
    const int l = h * WW + (w0 + ty);
    out[b * (NCH * HH * WW) + l * NCH + c] = y;
}

extern "C" void kernel_launch(void* const* d_in, const int* in_sizes, int n_in,
                              void* d_out, int out_size)
{
    const float* x      = (const float*)d_in[0];
    const float* mask   = (const float*)d_in[1];
    const float* weight = (const float*)d_in[2];
    const float* bias   = (const float*)d_in[3];
    float* out = (float*)d_out;

    const int B = in_sizes[0] / (3 * HH * WW);
    const int npix = B * HH * WW;
    dim3 grid(npix / PIX_PER_BLK);
    wos_kernel<<<grid, NTHREADS>>>(x, mask, weight, bias, out);
}